// round 4
// baseline (speedup 1.0000x reference)
#include <cuda_runtime.h>

// Problem constants
#define MDIM 65536      // 4*128*128 input pixels
#define KDIM 256        // input channels
#define NDIM 2304       // 9 taps * 256 out channels

// Scratch (device globals: allocation-free rule)
__device__ float g_Br[KDIM * NDIM];                  // weights transposed: [ci][t*256+co]
__device__ float g_z[(size_t)MDIM * NDIM];           // z = x @ Br  (604 MB)

// FIR/phase combination coefficients A[r][j+1][t]:
// out[2u+r] = sum_j sum_t A_r1[j1,t1]*A_r2[j2,t2] * z[u-j, t]
// Derived: q=(n-e+t)/2, j=(e-r-t)/2, coeff g[e], g=(.25,.75,.75,.25)
__device__ constexpr float AT[2][3][3] = {
    { {0.00f, 0.00f, 0.25f},    // r=0, j=-1  (reads z[u+1])
      {0.25f, 0.75f, 0.75f},    // r=0, j= 0
      {0.75f, 0.25f, 0.00f} },  // r=0, j=+1  (reads z[u-1])
    { {0.00f, 0.25f, 0.75f},    // r=1, j=-1
      {0.75f, 0.75f, 0.25f},    // r=1, j= 0
      {0.25f, 0.00f, 0.00f} }   // r=1, j=+1
};

// ---------------------------------------------------------------------------
// Kernel 1: Br[ci*2304 + t*256+co] = w[(t*256+ci)*256 + co]
// ---------------------------------------------------------------------------
__global__ void prep_kernel(const float* __restrict__ w) {
    int o = blockIdx.x * 256 + threadIdx.x;   // 0 .. 589823 (exact grid)
    int ci = o / NDIM;
    int n  = o - ci * NDIM;
    int tt = n >> 8;
    int co = n & 255;
    g_Br[o] = w[(tt * 256 + ci) * 256 + co];
}

// ---------------------------------------------------------------------------
// Kernel 2: SGEMM  z[M=65536, N=2304] = x[M, K=256] @ Br[K, N]
// BM=128, BN=128, BK=16, 256 threads, 8x8 per thread
// ---------------------------------------------------------------------------
__global__ __launch_bounds__(256) void sgemm_kernel(const float* __restrict__ A) {
    __shared__ float As[16][132];   // padded rows
    __shared__ float Bs[16][132];

    const int n0 = blockIdx.x * 128;
    const int m0 = blockIdx.y * 128;
    const int tid = threadIdx.x;
    const int tx = tid & 15;
    const int ty = tid >> 4;

    float acc[8][8];
#pragma unroll
    for (int i = 0; i < 8; i++)
#pragma unroll
        for (int j = 0; j < 8; j++) acc[i][j] = 0.f;

    const int arow = tid >> 2;          // 0..63
    const int acol = (tid & 3) << 2;    // 0,4,8,12
    const int brow = tid >> 5;          // 0..7
    const int bcol = (tid & 31) << 2;   // 0..124

    for (int k0 = 0; k0 < KDIM; k0 += 16) {
#pragma unroll
        for (int h = 0; h < 2; h++) {
            int r = arow + h * 64;
            const float4 v = *(const float4*)(A + (size_t)(m0 + r) * KDIM + k0 + acol);
            As[acol + 0][r] = v.x;
            As[acol + 1][r] = v.y;
            As[acol + 2][r] = v.z;
            As[acol + 3][r] = v.w;
        }
#pragma unroll
        for (int h = 0; h < 2; h++) {
            int r = brow + h * 8;
            const float4 v = *(const float4*)(g_Br + (size_t)(k0 + r) * NDIM + n0 + bcol);
            *(float4*)&Bs[r][bcol] = v;
        }
        __syncthreads();

#pragma unroll
        for (int k = 0; k < 16; k++) {
            float ra[8], rb[8];
            const float4 a0 = *(const float4*)&As[k][ty * 8];
            const float4 a1 = *(const float4*)&As[k][ty * 8 + 4];
            const float4 b0 = *(const float4*)&Bs[k][tx * 8];
            const float4 b1 = *(const float4*)&Bs[k][tx * 8 + 4];
            ra[0]=a0.x; ra[1]=a0.y; ra[2]=a0.z; ra[3]=a0.w;
            ra[4]=a1.x; ra[5]=a1.y; ra[6]=a1.z; ra[7]=a1.w;
            rb[0]=b0.x; rb[1]=b0.y; rb[2]=b0.z; rb[3]=b0.w;
            rb[4]=b1.x; rb[5]=b1.y; rb[6]=b1.z; rb[7]=b1.w;
#pragma unroll
            for (int i = 0; i < 8; i++)
#pragma unroll
                for (int j = 0; j < 8; j++)
                    acc[i][j] = fmaf(ra[i], rb[j], acc[i][j]);
        }
        __syncthreads();
    }

#pragma unroll
    for (int i = 0; i < 8; i++) {
        size_t row = (size_t)(m0 + ty * 8 + i) * NDIM + n0 + tx * 8;
        *(float4*)(g_z + row)     = make_float4(acc[i][0], acc[i][1], acc[i][2], acc[i][3]);
        *(float4*)(g_z + row + 4) = make_float4(acc[i][4], acc[i][5], acc[i][6], acc[i][7]);
    }
}

// ---------------------------------------------------------------------------
// Kernel 3: combine z neighbors with constant FIR/phase coefficients -> out
// Block: u-tile 8x8 (=> 16x16 output pixels), 32 out-channels.
// smem: z[10][10][9][32] = 115200 B (dynamic)
// ---------------------------------------------------------------------------
__global__ __launch_bounds__(256) void combine_kernel(const float* __restrict__ bias,
                                                      float* __restrict__ out) {
    extern __shared__ float zs[];   // [(l1*10 + l2)*9 + tt]*32 + co

    const int co0 = blockIdx.x * 32;
    const int T2  = blockIdx.y;           // 0..15
    const int bz  = blockIdx.z;           // b*16 + T1
    const int b   = bz >> 4;
    const int T1  = bz & 15;
    const int u10 = T1 * 8, u20 = T2 * 8;
    const int tid = threadIdx.x;

    // Load z tile (with 1-halo, zero outside [0,128))
    const int TOT = 10 * 10 * 9 * 32;     // 28800
    for (int e = tid; e < TOT; e += 256) {
        int co = e & 31;
        int tt = (e >> 5) % 9;
        int l2 = (e / 288) % 10;
        int l1 = e / 2880;
        int u1 = u10 + l1 - 1;
        int u2 = u20 + l2 - 1;
        float v = 0.f;
        if ((unsigned)u1 < 128u && (unsigned)u2 < 128u)
            v = g_z[(size_t)((b * 128 + u1) * 128 + u2) * NDIM + tt * 256 + co0 + co];
        zs[e] = v;
    }
    __syncthreads();

    const int co = tid & 31;
    const int c1 = tid >> 5;              // 0..7 : u1 within tile
    const float bv = bias[co0 + co];

    for (int c2 = 0; c2 < 8; c2++) {
        float a00 = 0.f, a01 = 0.f, a10 = 0.f, a11 = 0.f;
#pragma unroll
        for (int dj1 = 0; dj1 < 3; dj1++)
#pragma unroll
        for (int t1 = 0; t1 < 3; t1++) {
            const float w0 = AT[0][dj1][t1];
            const float w1 = AT[1][dj1][t1];
            if (w0 == 0.f && w1 == 0.f) continue;   // folded at compile time
            const int l1 = c1 + 2 - dj1;
#pragma unroll
            for (int dj2 = 0; dj2 < 3; dj2++)
#pragma unroll
            for (int t2 = 0; t2 < 3; t2++) {
                const float v0 = AT[0][dj2][t2];
                const float v1 = AT[1][dj2][t2];
                if (v0 == 0.f && v1 == 0.f) continue;
                const int l2 = c2 + 2 - dj2;
                const float zv = zs[((l1 * 10 + l2) * 9 + t1 * 3 + t2) * 32 + co];
                if (w0 * v0 != 0.f) a00 = fmaf(w0 * v0, zv, a00);
                if (w0 * v1 != 0.f) a01 = fmaf(w0 * v1, zv, a01);
                if (w1 * v0 != 0.f) a10 = fmaf(w1 * v0, zv, a10);
                if (w1 * v1 != 0.f) a11 = fmaf(w1 * v1, zv, a11);
            }
        }
        const int o1 = 2 * (u10 + c1);
        const int o2 = 2 * (u20 + c2);
        const size_t base = (((size_t)b * 256 + o1) * 256 + o2) * 256 + co0 + co;
        out[base]                   = a00 + bv;   // (even, even)
        out[base + 256]             = a01 + bv;   // (even, odd)
        out[base + 256 * 256]       = a10 + bv;   // (odd,  even)
        out[base + 256 * 256 + 256] = a11 + bv;
    }
}

// ---------------------------------------------------------------------------
extern "C" void kernel_launch(void* const* d_in, const int* in_sizes, int n_in,
                              void* d_out, int out_size) {
    const float* x = (const float*)d_in[0];   // [4,128,128,256]
    const float* w = (const float*)d_in[1];   // [3,3,256,256]
    const float* b = (const float*)d_in[2];   // [256]
    float* out = (float*)d_out;               // [4,256,256,256]

    // 1) weight transpose
    prep_kernel<<<(KDIM * NDIM) / 256, 256>>>(w);

    // 2) z = x @ Br
    dim3 ggrid(NDIM / 128, MDIM / 128);
    sgemm_kernel<<<ggrid, 256>>>(x);

    // 3) FIR/phase combine + bias
    cudaFuncSetAttribute(combine_kernel,
                         cudaFuncAttributeMaxDynamicSharedMemorySize, 115200);
    dim3 cgrid(8, 16, 64);  // co-chunks, T2, b*16+T1
    combine_kernel<<<cgrid, 256, 115200>>>(b, out);
}

// round 7
// speedup vs baseline: 1.4236x; 1.4236x over previous
#include <cuda_runtime.h>
#include <cuda_bf16.h>
#include <cstdint>

#define MDIM 65536      // 4*128*128 input pixels
#define KDIM 256        // input channels
#define NDIM 2304       // 9 taps * 256 out channels

// Scratch (device globals: allocation-free rule)
__device__ float g_z[(size_t)MDIM * NDIM];                 // z = x @ B^T (604 MB)
__device__ __nv_bfloat16 g_Bhi[(size_t)NDIM * KDIM];       // B[n=(t,co)][ci] hi
__device__ __nv_bfloat16 g_Blo[(size_t)NDIM * KDIM];       // B[n=(t,co)][ci] lo
__device__ __nv_bfloat16 g_xhi[(size_t)MDIM * KDIM];       // x hi  [m][ci]
__device__ __nv_bfloat16 g_xlo[(size_t)MDIM * KDIM];       // x lo  [m][ci]

__device__ __forceinline__ uint32_t smem_to_u32(const void* p) {
    uint32_t a;
    asm("{ .reg .u64 t; cvta.to.shared.u64 t, %1; cvt.u32.u64 %0, t; }" : "=r"(a) : "l"(p));
    return a;
}
__device__ __forceinline__ void cp_async16(uint32_t dst, const void* src) {
    asm volatile("cp.async.cg.shared.global [%0], [%1], 16;"
                 :: "r"(dst), "l"(__cvta_generic_to_global(src)));
}
#define CP_COMMIT() asm volatile("cp.async.commit_group;" ::: "memory")
#define CP_WAIT(N)  asm volatile("cp.async.wait_group %0;" :: "n"(N) : "memory")

#define LDMATRIX_X4(r0, r1, r2, r3, addr) \
    asm volatile("ldmatrix.sync.aligned.m8n8.x4.shared.b16 {%0,%1,%2,%3}, [%4];" \
                 : "=r"(r0), "=r"(r1), "=r"(r2), "=r"(r3) : "r"(addr))

__device__ __forceinline__ void mma16816(float* d, const uint32_t* a,
                                         uint32_t b0, uint32_t b1) {
    asm volatile(
        "mma.sync.aligned.m16n8k16.row.col.f32.bf16.bf16.f32 "
        "{%0,%1,%2,%3}, {%4,%5,%6,%7}, {%8,%9}, {%0,%1,%2,%3};"
        : "+f"(d[0]), "+f"(d[1]), "+f"(d[2]), "+f"(d[3])
        : "r"(a[0]), "r"(a[1]), "r"(a[2]), "r"(a[3]), "r"(b0), "r"(b1));
}

// ---------------------------------------------------------------------------
// FIR/phase coefficients: out[2u+r] = sum_j,t A_r1[j1,t1]*A_r2[j2,t2]*z[u-j,t]
__device__ constexpr float AT[2][3][3] = {
    { {0.00f, 0.00f, 0.25f},
      {0.25f, 0.75f, 0.75f},
      {0.75f, 0.25f, 0.00f} },
    { {0.00f, 0.25f, 0.75f},
      {0.75f, 0.75f, 0.25f},
      {0.25f, 0.00f, 0.00f} }
};

// ---------------------------------------------------------------------------
// Kernel 1a: bf16 hi/lo split of B[n=(t,co)][ci] = w[t][ci][co]
// ---------------------------------------------------------------------------
__global__ void prep_w_kernel(const float* __restrict__ w) {
    int o = blockIdx.x * 256 + threadIdx.x;   // 0 .. 589823
    int n  = o >> 8;
    int ci = o & 255;
    int tt = n >> 8;
    int co = n & 255;
    float v = w[(tt * 256 + ci) * 256 + co];
    __nv_bfloat16 h = __float2bfloat16_rn(v);
    float rem = v - __bfloat162float(h);
    g_Bhi[(size_t)n * KDIM + ci] = h;
    g_Blo[(size_t)n * KDIM + ci] = __float2bfloat16_rn(rem);
}

// ---------------------------------------------------------------------------
// Kernel 1b: bf16 hi/lo split of x (same [m][ci] layout)
// ---------------------------------------------------------------------------
__global__ void prep_x_kernel(const float* __restrict__ x) {
    size_t i = ((size_t)blockIdx.x * 256 + threadIdx.x) * 4;
    const float4 v = *(const float4*)(x + i);
    __nv_bfloat162 h01 = __floats2bfloat162_rn(v.x, v.y);
    __nv_bfloat162 h23 = __floats2bfloat162_rn(v.z, v.w);
    float2 f01 = __bfloat1622float2(h01);
    float2 f23 = __bfloat1622float2(h23);
    __nv_bfloat162 l01 = __floats2bfloat162_rn(v.x - f01.x, v.y - f01.y);
    __nv_bfloat162 l23 = __floats2bfloat162_rn(v.z - f23.x, v.w - f23.y);
    *(uint2*)&g_xhi[i] = make_uint2(*(uint32_t*)&h01, *(uint32_t*)&h23);
    *(uint2*)&g_xlo[i] = make_uint2(*(uint32_t*)&l01, *(uint32_t*)&l23);
}

// ---------------------------------------------------------------------------
// Kernel 2: mma.sync bf16 GEMM  z[65536,2304] = [xhi|xlo|xhi] @ [Bhi|Bhi|Blo]^T
// CTA tile 128x128, BK=32, 3-stage cp.async pipeline, warps 4(m) x 2(n).
// K_eff = 768 (24 iters).  smem rows padded to 40 elems (conflict-free ldmatrix).
// ---------------------------------------------------------------------------
#define BK 32
#define LDSR 40                       // padded row stride (elems)
#define STG_ELEMS (128 * LDSR)        // 5120 elems = 10240 B per operand-stage
#define A_OFF(s) ((s) * STG_ELEMS)
#define B_OFF(s) ((3 + (s)) * STG_ELEMS)
#define GSMEM_BYTES (6 * STG_ELEMS * 2)   // 61440

__global__ __launch_bounds__(256) void gemm_kernel() {
    extern __shared__ __nv_bfloat16 smem[];
    const uint32_t sb = smem_to_u32(smem);
    const int tid = threadIdx.x;
    const int lane = tid & 31;
    const int wid = tid >> 5;
    const int n0 = blockIdx.x * 128;
    const int m0 = blockIdx.y * 128;
    const int wm = (wid >> 1) * 32;       // warp m offset
    const int wn = (wid & 1) * 64;        // warp n offset

    // stage loader: kk = global k start (0..736, step 32)
    auto load_stage = [&](int stage, int kk) {
        const __nv_bfloat16* asrc = (kk < 256) ? g_xhi : ((kk < 512) ? g_xlo : g_xhi);
        const __nv_bfloat16* bsrc = (kk < 512) ? g_Bhi : g_Blo;
        const int col = kk & 255;
#pragma unroll
        for (int h = 0; h < 2; h++) {
            int c16 = tid * 2 + h;            // 0..511
            int row = c16 >> 2;               // 0..127
            int jc  = (c16 & 3) << 3;         // 0,8,16,24 elems
            uint32_t soff = (uint32_t)((row * LDSR + jc) * 2);
            cp_async16(sb + A_OFF(stage) * 2 + soff,
                       asrc + (size_t)(m0 + row) * KDIM + col + jc);
            cp_async16(sb + B_OFF(stage) * 2 + soff,
                       bsrc + (size_t)(n0 + row) * KDIM + col + jc);
        }
        CP_COMMIT();
    };

    float d[2][8][4];
#pragma unroll
    for (int i = 0; i < 2; i++)
#pragma unroll
        for (int j = 0; j < 8; j++)
#pragma unroll
            for (int q = 0; q < 4; q++) d[i][j][q] = 0.f;

    load_stage(0, 0);
    load_stage(1, BK);

    for (int it = 0; it < 24; it++) {
        if (it < 23) { CP_WAIT(1); } else { CP_WAIT(0); }
        __syncthreads();
        if (it + 2 < 24) load_stage((it + 2) % 3, (it + 2) * BK);

        const int s = it % 3;
        const uint32_t abase = sb + A_OFF(s) * 2;
        const uint32_t bbase = sb + B_OFF(s) * 2;
#pragma unroll
        for (int k16 = 0; k16 < 2; k16++) {
            const int kc = k16 * 16;
            uint32_t a[2][4];
#pragma unroll
            for (int mt = 0; mt < 2; mt++) {
                int r = wm + mt * 16 + (lane & 7) + ((lane >> 3) & 1) * 8;
                int c = kc + (lane >> 4) * 8;
                LDMATRIX_X4(a[mt][0], a[mt][1], a[mt][2], a[mt][3],
                            abase + (uint32_t)((r * LDSR + c) * 2));
            }
            uint32_t b[4][4];
#pragma unroll
            for (int nt = 0; nt < 4; nt++) {
                int rb = wn + nt * 16 + (lane & 7) + ((lane >> 4) & 1) * 8;
                int cb = kc + ((lane >> 3) & 1) * 8;
                LDMATRIX_X4(b[nt][0], b[nt][1], b[nt][2], b[nt][3],
                            bbase + (uint32_t)((rb * LDSR + cb) * 2));
            }
#pragma unroll
            for (int mt = 0; mt < 2; mt++)
#pragma unroll
                for (int nt = 0; nt < 4; nt++)
#pragma unroll
                    for (int h = 0; h < 2; h++)
                        mma16816(d[mt][nt * 2 + h], a[mt], b[nt][h * 2], b[nt][h * 2 + 1]);
        }
        __syncthreads();
    }

    // epilogue: d[mt][nt*2+h] rows: lane/4 (+8), cols: (lane%4)*2
#pragma unroll
    for (int mt = 0; mt < 2; mt++) {
        const int mrow = m0 + wm + mt * 16 + (lane >> 2);
#pragma unroll
        for (int j = 0; j < 8; j++) {
            const int ncol = n0 + wn + (j >> 1) * 16 + (j & 1) * 8 + (lane & 3) * 2;
            float* p0 = g_z + (size_t)mrow * NDIM + ncol;
            float* p1 = g_z + (size_t)(mrow + 8) * NDIM + ncol;
            *(float2*)p0 = make_float2(d[mt][j][0], d[mt][j][1]);
            *(float2*)p1 = make_float2(d[mt][j][2], d[mt][j][3]);
        }
    }
}

// ---------------------------------------------------------------------------
// Kernel 3: combine z neighbors with constant coefficients -> out
// ---------------------------------------------------------------------------
__global__ __launch_bounds__(256) void combine_kernel(const float* __restrict__ bias,
                                                      float* __restrict__ out) {
    extern __shared__ float zs[];

    const int co0 = blockIdx.x * 32;
    const int T2  = blockIdx.y;
    const int bz  = blockIdx.z;
    const int b   = bz >> 4;
    const int T1  = bz & 15;
    const int u10 = T1 * 8, u20 = T2 * 8;
    const int tid = threadIdx.x;

    const int TOT = 10 * 10 * 9 * 32;
    for (int e = tid; e < TOT; e += 256) {
        int co = e & 31;
        int tt = (e >> 5) % 9;
        int l2 = (e / 288) % 10;
        int l1 = e / 2880;
        int u1 = u10 + l1 - 1;
        int u2 = u20 + l2 - 1;
        float v = 0.f;
        if ((unsigned)u1 < 128u && (unsigned)u2 < 128u)
            v = g_z[(size_t)((b * 128 + u1) * 128 + u2) * NDIM + tt * 256 + co0 + co];
        zs[e] = v;
    }
    __syncthreads();

    const int co = tid & 31;
    const int c1 = tid >> 5;
    const float bv = bias[co0 + co];

    for (int c2 = 0; c2 < 8; c2++) {
        float a00 = 0.f, a01 = 0.f, a10 = 0.f, a11 = 0.f;
#pragma unroll
        for (int dj1 = 0; dj1 < 3; dj1++)
#pragma unroll
        for (int t1 = 0; t1 < 3; t1++) {
            const float w0 = AT[0][dj1][t1];
            const float w1 = AT[1][dj1][t1];
            if (w0 == 0.f && w1 == 0.f) continue;
            const int l1 = c1 + 2 - dj1;
#pragma unroll
            for (int dj2 = 0; dj2 < 3; dj2++)
#pragma unroll
            for (int t2 = 0; t2 < 3; t2++) {
                const float v0 = AT[0][dj2][t2];
                const float v1 = AT[1][dj2][t2];
                if (v0 == 0.f && v1 == 0.f) continue;
                const int l2 = c2 + 2 - dj2;
                const float zv = zs[((l1 * 10 + l2) * 9 + t1 * 3 + t2) * 32 + co];
                if (w0 * v0 != 0.f) a00 = fmaf(w0 * v0, zv, a00);
                if (w0 * v1 != 0.f) a01 = fmaf(w0 * v1, zv, a01);
                if (w1 * v0 != 0.f) a10 = fmaf(w1 * v0, zv, a10);
                if (w1 * v1 != 0.f) a11 = fmaf(w1 * v1, zv, a11);
            }
        }
        const int o1 = 2 * (u10 + c1);
        const int o2 = 2 * (u20 + c2);
        const size_t base = (((size_t)b * 256 + o1) * 256 + o2) * 256 + co0 + co;
        out[base]                   = a00 + bv;
        out[base + 256]             = a01 + bv;
        out[base + 256 * 256]       = a10 + bv;
        out[base + 256 * 256 + 256] = a11 + bv;
    }
}

// ---------------------------------------------------------------------------
extern "C" void kernel_launch(void* const* d_in, const int* in_sizes, int n_in,
                              void* d_out, int out_size) {
    const float* x = (const float*)d_in[0];   // [4,128,128,256]
    const float* w = (const float*)d_in[1];   // [3,3,256,256]
    const float* b = (const float*)d_in[2];   // [256]
    float* out = (float*)d_out;               // [4,256,256,256]

    prep_w_kernel<<<2304, 256>>>(w);
    prep_x_kernel<<<16384, 256>>>(x);

    cudaFuncSetAttribute(gemm_kernel,
                         cudaFuncAttributeMaxDynamicSharedMemorySize, GSMEM_BYTES);
    dim3 ggrid(NDIM / 128, MDIM / 128);       // (18, 512)
    gemm_kernel<<<ggrid, 256, GSMEM_BYTES>>>();

    cudaFuncSetAttribute(combine_kernel,
                         cudaFuncAttributeMaxDynamicSharedMemorySize, 115200);
    dim3 cgrid(8, 16, 64);
    combine_kernel<<<cgrid, 256, 115200>>>(b, out);
}

// round 8
// speedup vs baseline: 2.1737x; 1.5268x over previous
#include <cuda_runtime.h>
#include <cuda_bf16.h>
#include <cstdint>

#define MDIM 65536      // 4*128*128 input pixels
#define KDIM 256        // input channels
#define NDIM 2304       // 9 taps * 256 out channels

__device__ float g_z[(size_t)MDIM * NDIM];                 // z = x @ B^T (604 MB)
__device__ __nv_bfloat16 g_Bhi[(size_t)NDIM * KDIM];
__device__ __nv_bfloat16 g_Blo[(size_t)NDIM * KDIM];
__device__ __nv_bfloat16 g_xhi[(size_t)MDIM * KDIM];
__device__ __nv_bfloat16 g_xlo[(size_t)MDIM * KDIM];

__device__ __forceinline__ uint32_t smem_to_u32(const void* p) {
    uint32_t a;
    asm("{ .reg .u64 t; cvta.to.shared.u64 t, %1; cvt.u32.u64 %0, t; }" : "=r"(a) : "l"(p));
    return a;
}
__device__ __forceinline__ void cp_async16(uint32_t dst, const void* src) {
    asm volatile("cp.async.cg.shared.global [%0], [%1], 16;"
                 :: "r"(dst), "l"(__cvta_generic_to_global(src)));
}
__device__ __forceinline__ void cp_async4(uint32_t dst, const void* src) {
    asm volatile("cp.async.ca.shared.global [%0], [%1], 4;"
                 :: "r"(dst), "l"(__cvta_generic_to_global(src)));
}
#define CP_COMMIT() asm volatile("cp.async.commit_group;" ::: "memory")
#define CP_WAIT(N)  asm volatile("cp.async.wait_group %0;" :: "n"(N) : "memory")

#define LDMATRIX_X4(r0, r1, r2, r3, addr) \
    asm volatile("ldmatrix.sync.aligned.m8n8.x4.shared.b16 {%0,%1,%2,%3}, [%4];" \
                 : "=r"(r0), "=r"(r1), "=r"(r2), "=r"(r3) : "r"(addr))

__device__ __forceinline__ void mma16816(float* d, const uint32_t* a,
                                         uint32_t b0, uint32_t b1) {
    asm volatile(
        "mma.sync.aligned.m16n8k16.row.col.f32.bf16.bf16.f32 "
        "{%0,%1,%2,%3}, {%4,%5,%6,%7}, {%8,%9}, {%0,%1,%2,%3};"
        : "+f"(d[0]), "+f"(d[1]), "+f"(d[2]), "+f"(d[3])
        : "r"(a[0]), "r"(a[1]), "r"(a[2]), "r"(a[3]), "r"(b0), "r"(b1));
}

// FIR/phase coefficients: out[2u+r] = sum_j,t A_r1[j1,t1]*A_r2[j2,t2]*z[u-j,t]
__device__ constexpr float AT[2][3][3] = {
    { {0.00f, 0.00f, 0.25f},
      {0.25f, 0.75f, 0.75f},
      {0.75f, 0.25f, 0.00f} },
    { {0.00f, 0.25f, 0.75f},
      {0.75f, 0.75f, 0.25f},
      {0.25f, 0.00f, 0.00f} }
};

// ---------------------------------------------------------------------------
// Kernel 1a / 1b: bf16 hi/lo splits
// ---------------------------------------------------------------------------
__global__ void prep_w_kernel(const float* __restrict__ w) {
    int o = blockIdx.x * 256 + threadIdx.x;
    int n  = o >> 8;
    int ci = o & 255;
    int tt = n >> 8;
    int co = n & 255;
    float v = w[(tt * 256 + ci) * 256 + co];
    __nv_bfloat16 h = __float2bfloat16_rn(v);
    float rem = v - __bfloat162float(h);
    g_Bhi[(size_t)n * KDIM + ci] = h;
    g_Blo[(size_t)n * KDIM + ci] = __float2bfloat16_rn(rem);
}

__global__ void prep_x_kernel(const float* __restrict__ x) {
    size_t i = ((size_t)blockIdx.x * 256 + threadIdx.x) * 4;
    const float4 v = *(const float4*)(x + i);
    __nv_bfloat162 h01 = __floats2bfloat162_rn(v.x, v.y);
    __nv_bfloat162 h23 = __floats2bfloat162_rn(v.z, v.w);
    float2 f01 = __bfloat1622float2(h01);
    float2 f23 = __bfloat1622float2(h23);
    __nv_bfloat162 l01 = __floats2bfloat162_rn(v.x - f01.x, v.y - f01.y);
    __nv_bfloat162 l23 = __floats2bfloat162_rn(v.z - f23.x, v.w - f23.y);
    *(uint2*)&g_xhi[i] = make_uint2(*(uint32_t*)&h01, *(uint32_t*)&h23);
    *(uint2*)&g_xlo[i] = make_uint2(*(uint32_t*)&l01, *(uint32_t*)&l23);
}

// ---------------------------------------------------------------------------
// Kernel 2: mma.sync bf16 GEMM  z[65536,2304] = [xhi|xlo|xhi] @ [Bhi|Bhi|Blo]^T
// CTA 128x128, BK=64, 3-stage cp.async (prefetch distance 2 -> single sync/iter),
// 2 CTAs/SM.  K_eff = 768 (12 iters).
// ---------------------------------------------------------------------------
#define BK 64
#define LDSR 72                       // padded row stride (elems)
#define STG_ELEMS (128 * LDSR)        // 9216 elems = 18432 B per operand-stage
#define A_OFF(s) ((s) * STG_ELEMS)
#define B_OFF(s) ((3 + (s)) * STG_ELEMS)
#define GSMEM_BYTES (6 * STG_ELEMS * 2)   // 110592

__global__ __launch_bounds__(256, 2) void gemm_kernel() {
    extern __shared__ __nv_bfloat16 smem[];
    const uint32_t sb = smem_to_u32(smem);
    const int tid = threadIdx.x;
    const int lane = tid & 31;
    const int wid = tid >> 5;
    const int n0 = blockIdx.x * 128;
    const int m0 = blockIdx.y * 128;
    const int wm = (wid >> 1) * 32;
    const int wn = (wid & 1) * 64;

    auto load_stage = [&](int stage, int kk) {
        const __nv_bfloat16* asrc = (kk < 256) ? g_xhi : ((kk < 512) ? g_xlo : g_xhi);
        const __nv_bfloat16* bsrc = (kk < 512) ? g_Bhi : g_Blo;
        const int col = kk & 255;
#pragma unroll
        for (int h = 0; h < 4; h++) {
            int ch = h * 256 + tid;           // 0..1023 chunks of 16B
            int row = ch >> 3;
            int jc  = (ch & 7) << 3;          // elem offset in row
            uint32_t soff = (uint32_t)((row * LDSR + jc) * 2);
            cp_async16(sb + A_OFF(stage) * 2 + soff,
                       asrc + (size_t)(m0 + row) * KDIM + col + jc);
            cp_async16(sb + B_OFF(stage) * 2 + soff,
                       bsrc + (size_t)(n0 + row) * KDIM + col + jc);
        }
        CP_COMMIT();
    };

    float d[2][8][4];
#pragma unroll
    for (int i = 0; i < 2; i++)
#pragma unroll
        for (int j = 0; j < 8; j++)
#pragma unroll
            for (int q = 0; q < 4; q++) d[i][j][q] = 0.f;

    load_stage(0, 0);
    load_stage(1, BK);

    for (int it = 0; it < 12; it++) {
        if (it < 11) { CP_WAIT(1); } else { CP_WAIT(0); }
        __syncthreads();
        if (it + 2 < 12) load_stage((it + 2) % 3, (it + 2) * BK);

        const int s = it % 3;
        const uint32_t abase = sb + A_OFF(s) * 2;
        const uint32_t bbase = sb + B_OFF(s) * 2;
#pragma unroll
        for (int k16 = 0; k16 < 4; k16++) {
            const int kc = k16 * 16;
            uint32_t a[2][4];
#pragma unroll
            for (int mt = 0; mt < 2; mt++) {
                int r = wm + mt * 16 + (lane & 7) + ((lane >> 3) & 1) * 8;
                int c = kc + (lane >> 4) * 8;
                LDMATRIX_X4(a[mt][0], a[mt][1], a[mt][2], a[mt][3],
                            abase + (uint32_t)((r * LDSR + c) * 2));
            }
            uint32_t b[4][4];
#pragma unroll
            for (int nt = 0; nt < 4; nt++) {
                int rb = wn + nt * 16 + (lane & 7) + ((lane >> 4) & 1) * 8;
                int cb = kc + ((lane >> 3) & 1) * 8;
                LDMATRIX_X4(b[nt][0], b[nt][1], b[nt][2], b[nt][3],
                            bbase + (uint32_t)((rb * LDSR + cb) * 2));
            }
#pragma unroll
            for (int mt = 0; mt < 2; mt++)
#pragma unroll
                for (int nt = 0; nt < 4; nt++)
#pragma unroll
                    for (int h = 0; h < 2; h++)
                        mma16816(d[mt][nt * 2 + h], a[mt], b[nt][h * 2], b[nt][h * 2 + 1]);
        }
        // no bottom sync: next iter's prefetch targets stage (it+3)%3, which is
        // only reused after the top sync of that iteration.
    }

#pragma unroll
    for (int mt = 0; mt < 2; mt++) {
        const int mrow = m0 + wm + mt * 16 + (lane >> 2);
#pragma unroll
        for (int j = 0; j < 8; j++) {
            const int ncol = n0 + wn + (j >> 1) * 16 + (j & 1) * 8 + (lane & 3) * 2;
            float* p0 = g_z + (size_t)mrow * NDIM + ncol;
            float* p1 = g_z + (size_t)(mrow + 8) * NDIM + ncol;
            *(float2*)p0 = make_float2(d[mt][j][0], d[mt][j][1]);
            *(float2*)p1 = make_float2(d[mt][j][2], d[mt][j][3]);
        }
    }
}

// ---------------------------------------------------------------------------
// Kernel 3: combine.  512 threads; cp.async tile load; literal-offset LDS.
// Tile: u 8x8 (16x16 out), 32 channels. smem z[10][10][9][32] = 115200 B.
// ---------------------------------------------------------------------------
__global__ __launch_bounds__(512) void combine_kernel(const float* __restrict__ bias,
                                                      float* __restrict__ out) {
    extern __shared__ float zs[];
    const uint32_t zsb = smem_to_u32(zs);

    const int co0 = blockIdx.x * 32;
    const int T2  = blockIdx.y;
    const int bz  = blockIdx.z;
    const int b   = bz >> 4;
    const int T1  = bz & 15;
    const int u10 = T1 * 8, u20 = T2 * 8;
    const int tid = threadIdx.x;
    const int lane = tid & 31;
    const int warp = tid >> 5;

    // ---- async tile load: 900 cells (l1,l2,t), one warp per cell, 4B/lane ----
#pragma unroll 4
    for (int c = warp; c < 900; c += 16) {
        int l1 = c / 90;
        int rem = c - l1 * 90;
        int l2 = rem / 9;
        int t  = rem - l2 * 9;
        int u1 = u10 + l1 - 1;
        int u2 = u20 + l2 - 1;
        uint32_t dst = zsb + (uint32_t)(c * 32 + lane) * 4;
        if ((unsigned)u1 < 128u && (unsigned)u2 < 128u) {
            const float* src = g_z + (size_t)((b * 128 + u1) * 128 + u2) * NDIM
                                   + t * 256 + co0 + lane;
            cp_async4(dst, src);
        } else {
            zs[c * 32 + lane] = 0.f;
        }
    }
    CP_COMMIT();
    CP_WAIT(0);
    __syncthreads();

    // ---- compute: thread = (half, c1, co); c2 = half*4 + q ----
    const int co = lane;
    const int c1 = warp & 7;
    const int half = warp >> 3;          // 0..1
    const float bv = bias[co0 + co];

    const int o1 = 2 * (u10 + c1);
    size_t obase = (((size_t)(b * 256 + o1)) * 256 + 2 * u20 + half * 8) * 256 + co0 + co;

#pragma unroll
    for (int q = 0; q < 4; q++) {
        const int c2 = half * 4 + q;
        const float* zp = zs + (c1 * 10 + c2) * 288 + co;
        float a00 = 0.f, a01 = 0.f, a10 = 0.f, a11 = 0.f;
#pragma unroll
        for (int dj1 = 0; dj1 < 3; dj1++)
#pragma unroll
        for (int t1 = 0; t1 < 3; t1++) {
            const float w0 = AT[0][dj1][t1];
            const float w1 = AT[1][dj1][t1];
            if (w0 == 0.f && w1 == 0.f) continue;
#pragma unroll
            for (int dj2 = 0; dj2 < 3; dj2++)
#pragma unroll
            for (int t2 = 0; t2 < 3; t2++) {
                const float v0 = AT[0][dj2][t2];
                const float v1 = AT[1][dj2][t2];
                if (v0 == 0.f && v1 == 0.f) continue;
                const int IDX = ((((2 - dj1) * 10) + (2 - dj2)) * 9 + t1 * 3 + t2) * 32;
                const float zv = zp[IDX];
                if (w0 * v0 != 0.f) a00 = fmaf(w0 * v0, zv, a00);
                if (w0 * v1 != 0.f) a01 = fmaf(w0 * v1, zv, a01);
                if (w1 * v0 != 0.f) a10 = fmaf(w1 * v0, zv, a10);
                if (w1 * v1 != 0.f) a11 = fmaf(w1 * v1, zv, a11);
            }
        }
        float* p = out + obase + (size_t)q * 512;
        p[0]             = a00 + bv;     // (even, even)
        p[256]           = a01 + bv;     // (even, odd)
        p[65536]         = a10 + bv;     // (odd,  even)
        p[65536 + 256]   = a11 + bv;     // (odd,  odd)
    }
}

// ---------------------------------------------------------------------------
extern "C" void kernel_launch(void* const* d_in, const int* in_sizes, int n_in,
                              void* d_out, int out_size) {
    const float* x = (const float*)d_in[0];   // [4,128,128,256]
    const float* w = (const float*)d_in[1];   // [3,3,256,256]
    const float* b = (const float*)d_in[2];   // [256]
    float* out = (float*)d_out;               // [4,256,256,256]

    prep_w_kernel<<<2304, 256>>>(w);
    prep_x_kernel<<<16384, 256>>>(x);

    cudaFuncSetAttribute(gemm_kernel,
                         cudaFuncAttributeMaxDynamicSharedMemorySize, GSMEM_BYTES);
    dim3 ggrid(NDIM / 128, MDIM / 128);       // (18, 512)
    gemm_kernel<<<ggrid, 256, GSMEM_BYTES>>>();

    cudaFuncSetAttribute(combine_kernel,
                         cudaFuncAttributeMaxDynamicSharedMemorySize, 115200);
    dim3 cgrid(8, 16, 64);
    combine_kernel<<<cgrid, 512, 115200>>>(b, out);
}